// round 4
// baseline (speedup 1.0000x reference)
#include <cuda_runtime.h>
#include <cuda_bf16.h>

#define B_    4096
#define DIN_  784
#define DZ_   128
#define T_    256
#define BZ_   (B_*DZ_)

// scratch: 1/rate per (b,z)   (device global — no allocation)
__device__ float g_inv_rate[BZ_];

// ---------------------------------------------------------------------------
// Kernel 1: du = min(x@W_enc + b_enc, 5), inv_rate = 1/(exp(min(du+min(prior,5),5))+1e-6)
// tiled fp32 GEMM: BM=32, BN=128(=DZ), BK=16, 256 threads, 4x4 micro-tile
// ---------------------------------------------------------------------------
__global__ void enc_kernel(const float* __restrict__ x,
                           const float* __restrict__ W,
                           const float* __restrict__ bias,
                           const float* __restrict__ prior,
                           float* __restrict__ du_out) {
    __shared__ float As[16][32];
    __shared__ float Bs[16][128];
    const int tid = threadIdx.x;
    const int bm  = blockIdx.x * 32;
    const int tx  = tid & 31;   // 32 col-threads * 4 cols = 128
    const int ty  = tid >> 5;   // 8 row-threads * 4 rows = 32
    const int row0 = ty * 4, col0 = tx * 4;

    float acc[4][4] = {};

    for (int k0 = 0; k0 < DIN_; k0 += 16) {
        // load x tile 32(m) x 16(k): 512 floats, 2 per thread
        #pragma unroll
        for (int i = 0; i < 2; i++) {
            int l = tid * 2 + i;
            int r = l >> 4, c = l & 15;
            As[c][r] = x[(bm + r) * DIN_ + k0 + c];
        }
        // load W tile 16(k) x 128(n): 2048 floats, 8 per thread
        #pragma unroll
        for (int i = 0; i < 8; i++) {
            int l = tid + i * 256;
            int kk = l >> 7, n = l & 127;
            Bs[kk][n] = W[(k0 + kk) * DZ_ + n];
        }
        __syncthreads();
        #pragma unroll
        for (int kk = 0; kk < 16; kk++) {
            float a[4], b[4];
            #pragma unroll
            for (int i = 0; i < 4; i++) a[i] = As[kk][row0 + i];
            #pragma unroll
            for (int j = 0; j < 4; j++) b[j] = Bs[kk][col0 + j];
            #pragma unroll
            for (int i = 0; i < 4; i++)
                #pragma unroll
                for (int j = 0; j < 4; j++)
                    acc[i][j] = fmaf(a[i], b[j], acc[i][j]);
        }
        __syncthreads();
    }

    #pragma unroll
    for (int i = 0; i < 4; i++) {
        int r = bm + row0 + i;
        #pragma unroll
        for (int j = 0; j < 4; j++) {
            int n = col0 + j;
            float du = fminf(acc[i][j] + bias[n], 5.0f);
            du_out[r * DZ_ + n] = du;
            float lr = fminf(du + fminf(prior[n], 5.0f), 5.0f);
            float rate = __expf(lr) + 1e-6f;
            g_inv_rate[r * DZ_ + n] = 1.0f / rate;   // IEEE div, only 524k elems
        }
    }
}

// ---------------------------------------------------------------------------
// Kernel 2: exponential race. One thread per (b,z); serial cumsum over T=256.
//   e      = -log(1-u)
//   times += e * inv_rate
//   z     += sigmoid(1 - times) = 1/(1+exp(times-1))
// ---------------------------------------------------------------------------
__global__ void __launch_bounds__(256) race_kernel(const float* __restrict__ u,
                                                   float* __restrict__ z_out) {
    const int gid = blockIdx.x * 256 + threadIdx.x;   // 0..BZ_-1
    const float inv = g_inv_rate[gid];
    const float* up = u + gid;

    float times = 0.0f;
    float zacc  = 0.0f;

    #pragma unroll 8
    for (int t = 0; t < T_; t++) {
        float uu = __ldg(up + (size_t)t * BZ_);
        float e  = -__logf(1.0f - uu);                // 1-u exact (Sterbenz)
        times    = fmaf(e, inv, times);
        float ex = __expf(times - 1.0f);
        zacc    += __fdividef(1.0f, 1.0f + ex);       // sigmoid(1-times)
    }
    z_out[gid] = zacc;
}

// ---------------------------------------------------------------------------
// Kernel 3: y = sigmoid(z@W_dec + b_dec)
// BM=64, BN=64, BK=16, 256 threads, 4x4 micro-tile, N-edge guarded (784)
// ---------------------------------------------------------------------------
__global__ void dec_kernel(const float* __restrict__ z,
                           const float* __restrict__ W,
                           const float* __restrict__ bias,
                           float* __restrict__ y) {
    __shared__ float As[16][64];
    __shared__ float Bs[16][64];
    const int tid = threadIdx.x;
    const int bm = blockIdx.y * 64;
    const int bn = blockIdx.x * 64;
    const int tx = tid & 15;   // 16 col-threads * 4 = 64
    const int ty = tid >> 4;   // 16 row-threads * 4 = 64
    const int row0 = ty * 4, col0 = tx * 4;

    float acc[4][4] = {};

    for (int k0 = 0; k0 < DZ_; k0 += 16) {
        // z tile 64(m) x 16(k): 1024 floats, 4/thread
        #pragma unroll
        for (int i = 0; i < 4; i++) {
            int l = tid * 4 + i;          // consecutive k per thread (coalesced rows)
            int r = l >> 4, c = l & 15;
            As[c][r] = z[(bm + r) * DZ_ + k0 + c];
        }
        // W tile 16(k) x 64(n): 1024 floats, 4/thread, guard n edge
        #pragma unroll
        for (int i = 0; i < 4; i++) {
            int l = tid + i * 256;
            int kk = l >> 6, n = l & 63;
            int gn = bn + n;
            Bs[kk][n] = (gn < DIN_) ? W[(k0 + kk) * DIN_ + gn] : 0.0f;
        }
        __syncthreads();
        #pragma unroll
        for (int kk = 0; kk < 16; kk++) {
            float a[4], b[4];
            #pragma unroll
            for (int i = 0; i < 4; i++) a[i] = As[kk][row0 + i];
            #pragma unroll
            for (int j = 0; j < 4; j++) b[j] = Bs[kk][col0 + j];
            #pragma unroll
            for (int i = 0; i < 4; i++)
                #pragma unroll
                for (int j = 0; j < 4; j++)
                    acc[i][j] = fmaf(a[i], b[j], acc[i][j]);
        }
        __syncthreads();
    }

    #pragma unroll
    for (int i = 0; i < 4; i++) {
        int r = bm + row0 + i;
        #pragma unroll
        for (int j = 0; j < 4; j++) {
            int gn = bn + col0 + j;
            if (gn < DIN_) {
                float v = acc[i][j] + bias[gn];
                float ex = __expf(-v);
                y[r * DIN_ + gn] = __fdividef(1.0f, 1.0f + ex);
            }
        }
    }
}

// ---------------------------------------------------------------------------
// launch
// inputs (metadata order): x, u, W_enc, b_enc, W_dec, b_dec, prior
// output: concat(du [B,DZ], z [B,DZ], y [B,DIN])
// ---------------------------------------------------------------------------
extern "C" void kernel_launch(void* const* d_in, const int* in_sizes, int n_in,
                              void* d_out, int out_size) {
    const float* x     = (const float*)d_in[0];
    const float* u     = (const float*)d_in[1];
    const float* W_enc = (const float*)d_in[2];
    const float* b_enc = (const float*)d_in[3];
    const float* W_dec = (const float*)d_in[4];
    const float* b_dec = (const float*)d_in[5];
    const float* prior = (const float*)d_in[6];

    float* out_du = (float*)d_out;
    float* out_z  = out_du + BZ_;
    float* out_y  = out_z  + BZ_;

    // 1. encoder GEMM + rate
    enc_kernel<<<B_ / 32, 256>>>(x, W_enc, b_enc, prior, out_du);

    // 2. exponential race (dominant)
    race_kernel<<<BZ_ / 256, 256>>>(u, out_z);

    // 3. decoder GEMM + sigmoid
    dim3 g3((DIN_ + 63) / 64, B_ / 64);
    dec_kernel<<<g3, 256>>>(out_z, W_dec, b_dec, out_y);
}

// round 10
// speedup vs baseline: 1.4875x; 1.4875x over previous
#include <cuda_runtime.h>
#include <cuda_bf16.h>

#define B_    4096
#define DIN_  784
#define DZ_   128
#define T_    256
#define BZ_   (B_*DZ_)

// scratch: 1/rate per (b,z)   (device global — no allocation)
__device__ float g_inv_rate[BZ_];

// ---------------------------------------------------------------------------
// Kernel 1: du = min(x@W_enc + b_enc, 5); inv_rate = 1/(exp(min(du+min(prior,5),5))+1e-6)
// BM=32, BN=64, BK=32, 128 threads, 4x4 micro-tile, grid (128, 2).
// DIN_=784 = 24*32 + 16  ->  last K-tile is partial; masked with zeros.
// ---------------------------------------------------------------------------
__global__ void __launch_bounds__(128) enc_kernel(const float* __restrict__ x,
                                                  const float* __restrict__ W,
                                                  const float* __restrict__ bias,
                                                  const float* __restrict__ prior,
                                                  float* __restrict__ du_out) {
    __shared__ __align__(16) float As[32][36];   // [m][k], padded
    __shared__ __align__(16) float Bs[32][64];   // [k][n]
    const int tid  = threadIdx.x;
    const int bm   = blockIdx.x * 32;
    const int bn   = blockIdx.y * 64;
    const int col0 = (tid & 15) * 4;   // 16 col-groups * 4
    const int row0 = (tid >> 4) * 4;   // 8 row-groups * 4

    float acc[4][4] = {};

    for (int k0 = 0; k0 < DIN_; k0 += 32) {
        const int krem = DIN_ - k0;            // >= 32 except last tile (16)
        // x tile 32(m) x 32(k) = 256 float4, 2 per thread (K-tail masked)
        #pragma unroll
        for (int j = 0; j < 2; j++) {
            int f = tid + j * 128;
            int r = f >> 3, c4 = (f & 7) * 4;
            float4 v = make_float4(0.f, 0.f, 0.f, 0.f);
            if (c4 < krem)                     // krem multiple of 16 -> whole vec valid
                v = *(const float4*)(x + (size_t)(bm + r) * DIN_ + k0 + c4);
            *(float4*)(&As[r][c4]) = v;
        }
        // W tile 32(k) x 64(n) = 512 float4, 4 per thread (K-tail masked)
        #pragma unroll
        for (int j = 0; j < 4; j++) {
            int f = tid + j * 128;
            int kk = f >> 4, n4 = (f & 15) * 4;
            float4 v = make_float4(0.f, 0.f, 0.f, 0.f);
            if (kk < krem)
                v = *(const float4*)(W + (size_t)(k0 + kk) * DZ_ + bn + n4);
            *(float4*)(&Bs[kk][n4]) = v;
        }
        __syncthreads();
        #pragma unroll
        for (int kk = 0; kk < 32; kk++) {
            float a[4];
            float4 b = *(const float4*)(&Bs[kk][col0]);
            #pragma unroll
            for (int i = 0; i < 4; i++) a[i] = As[row0 + i][kk];
            const float bb[4] = {b.x, b.y, b.z, b.w};
            #pragma unroll
            for (int i = 0; i < 4; i++)
                #pragma unroll
                for (int j = 0; j < 4; j++)
                    acc[i][j] = fmaf(a[i], bb[j], acc[i][j]);
        }
        __syncthreads();
    }

    #pragma unroll
    for (int i = 0; i < 4; i++) {
        int r = bm + row0 + i;
        #pragma unroll
        for (int j = 0; j < 4; j++) {
            int n = bn + col0 + j;
            float du = fminf(acc[i][j] + bias[n], 5.0f);
            du_out[(size_t)r * DZ_ + n] = du;
            float lr = fminf(du + fminf(prior[n], 5.0f), 5.0f);
            float rate = __expf(lr) + 1e-6f;
            g_inv_rate[(size_t)r * DZ_ + n] = 1.0f / rate;
        }
    }
}

// ---------------------------------------------------------------------------
// Kernel 2: exponential race with monotone early exit.
//   times is nondecreasing; once times > 16 for all 32 lanes, every remaining
//   sigmoid term < sigmoid(-15) ~ 3e-7; tail sum <= 256*3e-7 ~ 8e-5 absolute.
// ---------------------------------------------------------------------------
__global__ void __launch_bounds__(256) race_kernel(const float* __restrict__ u,
                                                   float* __restrict__ z_out) {
    const int gid = blockIdx.x * 256 + threadIdx.x;   // 0..BZ_-1
    const float inv = g_inv_rate[gid];
    const float* up = u + gid;

    float times = 0.0f;
    float zacc  = 0.0f;

    for (int t = 0; t < T_; t += 8) {
        float uu[8];
        #pragma unroll
        for (int i = 0; i < 8; i++)
            uu[i] = __ldg(up + (size_t)(t + i) * BZ_);
        #pragma unroll
        for (int i = 0; i < 8; i++) {
            float e = -__logf(1.0f - uu[i]);              // 1-u exact (Sterbenz)
            times   = fmaf(e, inv, times);
            float ex = __expf(times - 1.0f);              // inf -> sigmoid 0, safe
            zacc   += __fdividef(1.0f, 1.0f + ex);        // sigmoid(1-times)
        }
        if (__all_sync(0xffffffffu, times > 16.0f)) break;
    }
    z_out[gid] = zacc;
}

// ---------------------------------------------------------------------------
// Kernel 3: y = sigmoid(z@W_dec + b_dec)
// BM=32, BN=64, BK=32 (DZ_=128 % 32 == 0, no K tail); N-edge guarded.
// grid (128, 13)
// ---------------------------------------------------------------------------
__global__ void __launch_bounds__(128) dec_kernel(const float* __restrict__ z,
                                                  const float* __restrict__ W,
                                                  const float* __restrict__ bias,
                                                  float* __restrict__ y) {
    __shared__ __align__(16) float As[32][36];
    __shared__ __align__(16) float Bs[32][64];
    const int tid  = threadIdx.x;
    const int bm   = blockIdx.x * 32;
    const int bn   = blockIdx.y * 64;
    const int col0 = (tid & 15) * 4;
    const int row0 = (tid >> 4) * 4;

    float acc[4][4] = {};

    #pragma unroll
    for (int k0 = 0; k0 < DZ_; k0 += 32) {
        // z tile 32(m) x 32(k)
        #pragma unroll
        for (int j = 0; j < 2; j++) {
            int f = tid + j * 128;
            int r = f >> 3, c4 = (f & 7) * 4;
            float4 v = *(const float4*)(z + (size_t)(bm + r) * DZ_ + k0 + c4);
            *(float4*)(&As[r][c4]) = v;
        }
        // W tile 32(k) x 64(n), N-edge guarded (784 boundary is float4-aligned)
        #pragma unroll
        for (int j = 0; j < 4; j++) {
            int f = tid + j * 128;
            int kk = f >> 4, n4 = (f & 15) * 4;
            int gn = bn + n4;
            float4 v = make_float4(0.f, 0.f, 0.f, 0.f);
            if (gn < DIN_)
                v = *(const float4*)(W + (size_t)(k0 + kk) * DIN_ + gn);
            *(float4*)(&Bs[kk][n4]) = v;
        }
        __syncthreads();
        #pragma unroll
        for (int kk = 0; kk < 32; kk++) {
            float a[4];
            float4 b = *(const float4*)(&Bs[kk][col0]);
            #pragma unroll
            for (int i = 0; i < 4; i++) a[i] = As[row0 + i][kk];
            const float bb[4] = {b.x, b.y, b.z, b.w};
            #pragma unroll
            for (int i = 0; i < 4; i++)
                #pragma unroll
                for (int j = 0; j < 4; j++)
                    acc[i][j] = fmaf(a[i], bb[j], acc[i][j]);
        }
        __syncthreads();
    }

    #pragma unroll
    for (int i = 0; i < 4; i++) {
        int r = bm + row0 + i;
        #pragma unroll
        for (int j = 0; j < 4; j++) {
            int gn = bn + col0 + j;
            if (gn < DIN_) {
                float v = acc[i][j] + bias[gn];
                float ex = __expf(-v);
                y[(size_t)r * DIN_ + gn] = __fdividef(1.0f, 1.0f + ex);
            }
        }
    }
}

// ---------------------------------------------------------------------------
// launch — inputs: x, u, W_enc, b_enc, W_dec, b_dec, prior
// output: concat(du [B,DZ], z [B,DZ], y [B,DIN])
// ---------------------------------------------------------------------------
extern "C" void kernel_launch(void* const* d_in, const int* in_sizes, int n_in,
                              void* d_out, int out_size) {
    const float* x     = (const float*)d_in[0];
    const float* u     = (const float*)d_in[1];
    const float* W_enc = (const float*)d_in[2];
    const float* b_enc = (const float*)d_in[3];
    const float* W_dec = (const float*)d_in[4];
    const float* b_dec = (const float*)d_in[5];
    const float* prior = (const float*)d_in[6];

    float* out_du = (float*)d_out;
    float* out_z  = out_du + BZ_;
    float* out_y  = out_z  + BZ_;

    dim3 g1(B_ / 32, DZ_ / 64);
    enc_kernel<<<g1, 128>>>(x, W_enc, b_enc, prior, out_du);

    race_kernel<<<BZ_ / 256, 256>>>(u, out_z);

    dim3 g3(B_ / 32, (DIN_ + 63) / 64);
    dec_kernel<<<g3, 128>>>(out_z, W_dec, b_dec, out_y);
}